// round 1
// baseline (speedup 1.0000x reference)
#include <cuda_runtime.h>

// ----------------------------------------------------------------------------
// MultiHeadSelfAttention: B=16, N=1024, C=768, H=12, D=64
// fp32 baseline: QKV GEMM (+bias, scatter to [b,h,n,d]) -> flash attention ->
// proj GEMM (+bias). All scratch in __device__ globals (no allocations).
// ----------------------------------------------------------------------------

#define DIMC   768
#define HEADS  12
#define HD     64
#define BATCH  16
#define SEQ    1024
#define MROWS  (BATCH * SEQ)   // 16384
#define NQKV   (3 * DIMC)      // 2304

// Scratch (each ~50 MB)
__device__ float g_Q[(size_t)BATCH * HEADS * SEQ * HD];
__device__ float g_K[(size_t)BATCH * HEADS * SEQ * HD];
__device__ float g_V[(size_t)BATCH * HEADS * SEQ * HD];
__device__ float g_O[(size_t)MROWS * DIMC];

// ----------------------------------------------------------------------------
// SGEMM 128x128x8 tile, 256 threads, 8x8 per-thread microtile.
// A: [M,K] row-major, Wmat: [K,Ncols] row-major.
// ----------------------------------------------------------------------------

__global__ __launch_bounds__(256) void gemm_qkv_kernel(
    const float* __restrict__ X,
    const float* __restrict__ W,
    const float* __restrict__ bias)
{
    __shared__ float As[8][128];
    __shared__ float Bs[8][128];
    const int K  = DIMC;
    const int Nc = NQKV;

    const int t  = threadIdx.x;
    const int bm = blockIdx.y;
    const int bn = blockIdx.x;

    const int arow = t >> 1, acol = (t & 1) * 4;
    const int brow = t >> 5, bcol = (t & 31) * 4;

    const float* Ap = X + (size_t)(bm * 128 + arow) * K + acol;
    const float* Bp = W + (size_t)brow * Nc + bn * 128 + bcol;

    float acc[8][8];
    #pragma unroll
    for (int i = 0; i < 8; i++)
        #pragma unroll
        for (int j = 0; j < 8; j++) acc[i][j] = 0.f;

    const int tx = t & 15, ty = t >> 4;

    for (int k0 = 0; k0 < K; k0 += 8) {
        float4 av = *(const float4*)(Ap + k0);
        float4 bv = *(const float4*)(Bp + (size_t)k0 * Nc);
        As[acol + 0][arow] = av.x;
        As[acol + 1][arow] = av.y;
        As[acol + 2][arow] = av.z;
        As[acol + 3][arow] = av.w;
        *(float4*)&Bs[brow][bcol] = bv;
        __syncthreads();

        #pragma unroll
        for (int kk = 0; kk < 8; kk++) {
            float4 a0 = *(const float4*)&As[kk][ty * 8];
            float4 a1 = *(const float4*)&As[kk][ty * 8 + 4];
            float4 b0 = *(const float4*)&Bs[kk][tx * 8];
            float4 b1 = *(const float4*)&Bs[kk][tx * 8 + 4];
            float a[8] = {a0.x, a0.y, a0.z, a0.w, a1.x, a1.y, a1.z, a1.w};
            float b[8] = {b0.x, b0.y, b0.z, b0.w, b1.x, b1.y, b1.z, b1.w};
            #pragma unroll
            for (int i = 0; i < 8; i++)
                #pragma unroll
                for (int j = 0; j < 8; j++)
                    acc[i][j] += a[i] * b[j];
        }
        __syncthreads();
    }

    // Epilogue: add bias, scatter into g_Q/g_K/g_V[b][h][n][d]
    #pragma unroll
    for (int i = 0; i < 8; i++) {
        const int row = bm * 128 + ty * 8 + i;
        const int bb  = row >> 10;       // batch
        const int nn  = row & 1023;      // seq position
        #pragma unroll
        for (int j = 0; j < 8; j++) {
            const int col = bn * 128 + tx * 8 + j;
            const float v = acc[i][j] + bias[col];
            const int which = col / DIMC;          // uniform per block (768 % 128-aligned tiles)
            const int rem   = col - which * DIMC;
            const int h     = rem >> 6;
            const int d     = rem & 63;
            const size_t idx = (((size_t)(bb * HEADS + h)) * SEQ + nn) * HD + d;
            if (which == 0)      g_Q[idx] = v;
            else if (which == 1) g_K[idx] = v;
            else                 g_V[idx] = v;
        }
    }
}

__global__ __launch_bounds__(256) void gemm_proj_kernel(
    const float* __restrict__ W,
    const float* __restrict__ bias,
    float* __restrict__ out)
{
    __shared__ float As[8][128];
    __shared__ float Bs[8][128];
    const int K  = DIMC;
    const int Nc = DIMC;

    const int t  = threadIdx.x;
    const int bm = blockIdx.y;
    const int bn = blockIdx.x;

    const int arow = t >> 1, acol = (t & 1) * 4;
    const int brow = t >> 5, bcol = (t & 31) * 4;

    const float* Ap = g_O + (size_t)(bm * 128 + arow) * K + acol;
    const float* Bp = W + (size_t)brow * Nc + bn * 128 + bcol;

    float acc[8][8];
    #pragma unroll
    for (int i = 0; i < 8; i++)
        #pragma unroll
        for (int j = 0; j < 8; j++) acc[i][j] = 0.f;

    const int tx = t & 15, ty = t >> 4;

    for (int k0 = 0; k0 < K; k0 += 8) {
        float4 av = *(const float4*)(Ap + k0);
        float4 bv = *(const float4*)(Bp + (size_t)k0 * Nc);
        As[acol + 0][arow] = av.x;
        As[acol + 1][arow] = av.y;
        As[acol + 2][arow] = av.z;
        As[acol + 3][arow] = av.w;
        *(float4*)&Bs[brow][bcol] = bv;
        __syncthreads();

        #pragma unroll
        for (int kk = 0; kk < 8; kk++) {
            float4 a0 = *(const float4*)&As[kk][ty * 8];
            float4 a1 = *(const float4*)&As[kk][ty * 8 + 4];
            float4 b0 = *(const float4*)&Bs[kk][tx * 8];
            float4 b1 = *(const float4*)&Bs[kk][tx * 8 + 4];
            float a[8] = {a0.x, a0.y, a0.z, a0.w, a1.x, a1.y, a1.z, a1.w};
            float b[8] = {b0.x, b0.y, b0.z, b0.w, b1.x, b1.y, b1.z, b1.w};
            #pragma unroll
            for (int i = 0; i < 8; i++)
                #pragma unroll
                for (int j = 0; j < 8; j++)
                    acc[i][j] += a[i] * b[j];
        }
        __syncthreads();
    }

    #pragma unroll
    for (int i = 0; i < 8; i++) {
        const int row = bm * 128 + ty * 8 + i;
        #pragma unroll
        for (int j = 0; j < 8; j++) {
            const int col = bn * 128 + tx * 8 + j;
            out[(size_t)row * Nc + col] = acc[i][j] + bias[col];
        }
    }
}

// ----------------------------------------------------------------------------
// Flash attention, fp32, online softmax.
// Grid: (B*H, SEQ/64). Block: 128 threads.
// Thread t: q-row = t>>1 (within 64-row tile), half = t&1 owns 32 key columns.
// q row held in registers; K/V chunks (64x64) staged in smem.
// ----------------------------------------------------------------------------

__global__ __launch_bounds__(128) void attn_kernel()
{
    __shared__ float Ks[64 * 64];
    __shared__ float Vs[64 * 64];

    const int bh = blockIdx.x;      // b*HEADS + h
    const int qt = blockIdx.y;      // query tile
    const int t  = threadIdx.x;
    const int qr   = t >> 1;
    const int half = t & 1;

    const float* Qb = g_Q + (size_t)bh * SEQ * HD;
    const float* Kb = g_K + (size_t)bh * SEQ * HD;
    const float* Vb = g_V + (size_t)bh * SEQ * HD;

    // q row in registers
    float4 q4[16];
    {
        const float4* qsrc = (const float4*)(Qb + (size_t)(qt * 64 + qr) * HD);
        #pragma unroll
        for (int i = 0; i < 16; i++) q4[i] = qsrc[i];
    }

    float o[64];
    #pragma unroll
    for (int d = 0; d < 64; d++) o[d] = 0.f;
    float m = -1e30f, l = 0.f;
    const float scale = 0.125f;   // 64^-0.5

    for (int c = 0; c < 16; c++) {
        __syncthreads();   // previous chunk's readers done before overwrite
        {
            const float4* ks = (const float4*)(Kb + (size_t)c * 64 * HD);
            const float4* vs = (const float4*)(Vb + (size_t)c * 64 * HD);
            for (int i = t; i < 1024; i += 128) {
                ((float4*)Ks)[i] = ks[i];
                ((float4*)Vs)[i] = vs[i];
            }
        }
        __syncthreads();

        float p[32];
        float mloc = -1e30f;
        #pragma unroll
        for (int j = 0; j < 32; j++) {
            const int kc = half * 32 + j;
            const float4* kp = (const float4*)(Ks + kc * 64);
            float acc = 0.f;
            #pragma unroll
            for (int d4 = 0; d4 < 16; d4++) {
                float4 kv = kp[d4];
                acc += q4[d4].x * kv.x + q4[d4].y * kv.y
                     + q4[d4].z * kv.z + q4[d4].w * kv.w;
            }
            p[j] = acc * scale;
            mloc = fmaxf(mloc, p[j]);
        }
        // row max across the lane pair
        mloc = fmaxf(mloc, __shfl_xor_sync(0xffffffffu, mloc, 1));
        const float mnew = fmaxf(m, mloc);
        const float corr = __expf(m - mnew);

        float lsum = 0.f;
        #pragma unroll
        for (int j = 0; j < 32; j++) {
            p[j] = __expf(p[j] - mnew);
            lsum += p[j];
        }
        lsum += __shfl_xor_sync(0xffffffffu, lsum, 1);
        l = l * corr + lsum;
        m = mnew;

        #pragma unroll
        for (int d = 0; d < 64; d++) o[d] *= corr;

        #pragma unroll
        for (int j = 0; j < 32; j++) {
            const int kc = half * 32 + j;
            const float pv = p[j];
            const float4* vp = (const float4*)(Vs + kc * 64);
            #pragma unroll
            for (int d4 = 0; d4 < 16; d4++) {
                float4 vv = vp[d4];
                o[d4 * 4 + 0] += pv * vv.x;
                o[d4 * 4 + 1] += pv * vv.y;
                o[d4 * 4 + 2] += pv * vv.z;
                o[d4 * 4 + 3] += pv * vv.w;
            }
        }
    }

    // combine lane-pair partial outputs (each holds its half of key columns)
    #pragma unroll
    for (int d = 0; d < 64; d++)
        o[d] += __shfl_xor_sync(0xffffffffu, o[d], 1);

    const float inv = 1.f / l;
    const int b = bh / HEADS, h = bh % HEADS;
    const int qg = qt * 64 + qr;
    float* op = g_O + ((size_t)(b * SEQ + qg)) * DIMC + h * HD + half * 32;
    #pragma unroll
    for (int d = 0; d < 32; d++) op[d] = o[half * 32 + d] * inv;
}

// ----------------------------------------------------------------------------
// Launch
// ----------------------------------------------------------------------------

extern "C" void kernel_launch(void* const* d_in, const int* in_sizes, int n_in,
                              void* d_out, int out_size)
{
    const float* x      = (const float*)d_in[0];
    const float* w_qkv  = (const float*)d_in[1];
    const float* b_qkv  = (const float*)d_in[2];
    const float* w_proj = (const float*)d_in[3];
    const float* b_proj = (const float*)d_in[4];
    float* out = (float*)d_out;

    gemm_qkv_kernel<<<dim3(NQKV / 128, MROWS / 128), 256>>>(x, w_qkv, b_qkv);
    attn_kernel<<<dim3(BATCH * HEADS, SEQ / 64), 128>>>();
    gemm_proj_kernel<<<dim3(DIMC / 128, MROWS / 128), 256>>>(w_proj, b_proj, out);
}

// round 7
// speedup vs baseline: 1.0483x; 1.0483x over previous
#include <cuda_runtime.h>

// ----------------------------------------------------------------------------
// MultiHeadSelfAttention: B=16, N=1024, C=768, H=12, D=64
// R7: packed-fp32 (fma.rn.f32x2 / FFMA2) everywhere. Same structure as the
// passing R1 kernel (tiles, smem, occupancy); inner products use 2-wide
// packed fp32 FMA for ~2x fma-pipe throughput. No bf16, no MMA/wmma (every
// kernel using those tripped a 128MiB device-mem delta; fp32 path is clean).
// ----------------------------------------------------------------------------

#define DIMC   768
#define HEADS  12
#define HD     64
#define BATCH  16
#define SEQ    1024
#define MROWS  (BATCH * SEQ)   // 16384
#define NQKV   (3 * DIMC)      // 2304

__device__ float g_Q[(size_t)BATCH * HEADS * SEQ * HD];
__device__ float g_K[(size_t)BATCH * HEADS * SEQ * HD];
__device__ float g_V[(size_t)BATCH * HEADS * SEQ * HD];
__device__ float g_O[(size_t)MROWS * DIMC];

typedef unsigned long long ull;

// Packed fp32 helpers (Blackwell f32x2). No volatile: pure value ops.
#define PK2(out, lo, hi) asm("mov.b64 %0, {%1, %2};" : "=l"(out) : "f"(lo), "f"(hi))
#define UPK2(lo, hi, in) asm("mov.b64 {%0, %1}, %2;" : "=f"(lo), "=f"(hi) : "l"(in))
#define FMA2(acc, a, b)  asm("fma.rn.f32x2 %0, %1, %2, %0;" : "+l"(acc) : "l"(a), "l"(b))
#define MUL2(acc, s)     asm("mul.rn.f32x2 %0, %0, %1;" : "+l"(acc) : "l"(s))

// ----------------------------------------------------------------------------
// SGEMM 128x128x8 tile, 256 threads, 8x8 microtile, f32x2 inner product.
// Identical memory choreography to the validated R1 kernel.
// ----------------------------------------------------------------------------

__global__ __launch_bounds__(256) void gemm_qkv_kernel(
    const float* __restrict__ X,
    const float* __restrict__ W,
    const float* __restrict__ bias)
{
    __shared__ float As[8][128];
    __shared__ float Bs[8][128];
    const int K  = DIMC;
    const int Nc = NQKV;

    const int t  = threadIdx.x;
    const int bm = blockIdx.y;
    const int bn = blockIdx.x;

    const int arow = t >> 1, acol = (t & 1) * 4;
    const int brow = t >> 5, bcol = (t & 31) * 4;

    const float* Ap = X + (size_t)(bm * 128 + arow) * K + acol;
    const float* Bp = W + (size_t)brow * Nc + bn * 128 + bcol;

    ull acc2[8][4];
    #pragma unroll
    for (int i = 0; i < 8; i++)
        #pragma unroll
        for (int j = 0; j < 4; j++) acc2[i][j] = 0ull;

    const int tx = t & 15, ty = t >> 4;

    for (int k0 = 0; k0 < K; k0 += 8) {
        float4 av = *(const float4*)(Ap + k0);
        float4 bv = *(const float4*)(Bp + (size_t)k0 * Nc);
        As[acol + 0][arow] = av.x;
        As[acol + 1][arow] = av.y;
        As[acol + 2][arow] = av.z;
        As[acol + 3][arow] = av.w;
        *(float4*)&Bs[brow][bcol] = bv;
        __syncthreads();

        #pragma unroll
        for (int kk = 0; kk < 8; kk++) {
            float4 a0 = *(const float4*)&As[kk][ty * 8];
            float4 a1 = *(const float4*)&As[kk][ty * 8 + 4];
            float4 b0 = *(const float4*)&Bs[kk][tx * 8];
            float4 b1 = *(const float4*)&Bs[kk][tx * 8 + 4];
            ull ab[8];
            PK2(ab[0], a0.x, a0.x); PK2(ab[1], a0.y, a0.y);
            PK2(ab[2], a0.z, a0.z); PK2(ab[3], a0.w, a0.w);
            PK2(ab[4], a1.x, a1.x); PK2(ab[5], a1.y, a1.y);
            PK2(ab[6], a1.z, a1.z); PK2(ab[7], a1.w, a1.w);
            ull bp[4];
            PK2(bp[0], b0.x, b0.y); PK2(bp[1], b0.z, b0.w);
            PK2(bp[2], b1.x, b1.y); PK2(bp[3], b1.z, b1.w);
            #pragma unroll
            for (int i = 0; i < 8; i++)
                #pragma unroll
                for (int j = 0; j < 4; j++) {
                    ull tacc = acc2[i][j];
                    FMA2(tacc, ab[i], bp[j]);
                    acc2[i][j] = tacc;
                }
        }
        __syncthreads();
    }

    // Epilogue: unpack, add bias, scatter into g_Q/g_K/g_V[b][h][n][d]
    #pragma unroll
    for (int i = 0; i < 8; i++) {
        const int row = bm * 128 + ty * 8 + i;
        const int bb  = row >> 10;
        const int nn  = row & 1023;
        #pragma unroll
        for (int jp = 0; jp < 4; jp++) {
            float v0, v1;
            UPK2(v0, v1, acc2[i][jp]);
            #pragma unroll
            for (int e = 0; e < 2; e++) {
                const int col = bn * 128 + tx * 8 + 2 * jp + e;
                const float v = (e == 0 ? v0 : v1) + bias[col];
                const int which = col / DIMC;
                const int rem   = col - which * DIMC;
                const int h     = rem >> 6;
                const int d     = rem & 63;
                const size_t idx = (((size_t)(bb * HEADS + h)) * SEQ + nn) * HD + d;
                if (which == 0)      g_Q[idx] = v;
                else if (which == 1) g_K[idx] = v;
                else                 g_V[idx] = v;
            }
        }
    }
}

__global__ __launch_bounds__(256) void gemm_proj_kernel(
    const float* __restrict__ W,
    const float* __restrict__ bias,
    float* __restrict__ out)
{
    __shared__ float As[8][128];
    __shared__ float Bs[8][128];
    const int K  = DIMC;
    const int Nc = DIMC;

    const int t  = threadIdx.x;
    const int bm = blockIdx.y;
    const int bn = blockIdx.x;

    const int arow = t >> 1, acol = (t & 1) * 4;
    const int brow = t >> 5, bcol = (t & 31) * 4;

    const float* Ap = g_O + (size_t)(bm * 128 + arow) * K + acol;
    const float* Bp = W + (size_t)brow * Nc + bn * 128 + bcol;

    ull acc2[8][4];
    #pragma unroll
    for (int i = 0; i < 8; i++)
        #pragma unroll
        for (int j = 0; j < 4; j++) acc2[i][j] = 0ull;

    const int tx = t & 15, ty = t >> 4;

    for (int k0 = 0; k0 < K; k0 += 8) {
        float4 av = *(const float4*)(Ap + k0);
        float4 bv = *(const float4*)(Bp + (size_t)k0 * Nc);
        As[acol + 0][arow] = av.x;
        As[acol + 1][arow] = av.y;
        As[acol + 2][arow] = av.z;
        As[acol + 3][arow] = av.w;
        *(float4*)&Bs[brow][bcol] = bv;
        __syncthreads();

        #pragma unroll
        for (int kk = 0; kk < 8; kk++) {
            float4 a0 = *(const float4*)&As[kk][ty * 8];
            float4 a1 = *(const float4*)&As[kk][ty * 8 + 4];
            float4 b0 = *(const float4*)&Bs[kk][tx * 8];
            float4 b1 = *(const float4*)&Bs[kk][tx * 8 + 4];
            ull ab[8];
            PK2(ab[0], a0.x, a0.x); PK2(ab[1], a0.y, a0.y);
            PK2(ab[2], a0.z, a0.z); PK2(ab[3], a0.w, a0.w);
            PK2(ab[4], a1.x, a1.x); PK2(ab[5], a1.y, a1.y);
            PK2(ab[6], a1.z, a1.z); PK2(ab[7], a1.w, a1.w);
            ull bp[4];
            PK2(bp[0], b0.x, b0.y); PK2(bp[1], b0.z, b0.w);
            PK2(bp[2], b1.x, b1.y); PK2(bp[3], b1.z, b1.w);
            #pragma unroll
            for (int i = 0; i < 8; i++)
                #pragma unroll
                for (int j = 0; j < 4; j++) {
                    ull tacc = acc2[i][j];
                    FMA2(tacc, ab[i], bp[j]);
                    acc2[i][j] = tacc;
                }
        }
        __syncthreads();
    }

    #pragma unroll
    for (int i = 0; i < 8; i++) {
        const int row = bm * 128 + ty * 8 + i;
        #pragma unroll
        for (int jp = 0; jp < 4; jp++) {
            float v0, v1;
            UPK2(v0, v1, acc2[i][jp]);
            const int col = bn * 128 + tx * 8 + 2 * jp;
            out[(size_t)row * Nc + col]     = v0 + bias[col];
            out[(size_t)row * Nc + col + 1] = v1 + bias[col + 1];
        }
    }
}

// ----------------------------------------------------------------------------
// Flash attention, fp32 with f32x2 packed inner products.
// Grid (B*H, SEQ/64), 128 threads; thread t: q-row t>>1, half t&1.
// ----------------------------------------------------------------------------

__global__ __launch_bounds__(128) void attn_kernel()
{
    __shared__ float Ks[64 * 64];
    __shared__ float Vs[64 * 64];

    const int bh = blockIdx.x;
    const int qt = blockIdx.y;
    const int t  = threadIdx.x;
    const int qr   = t >> 1;
    const int half = t & 1;

    const float* Qb = g_Q + (size_t)bh * SEQ * HD;
    const float* Kb = g_K + (size_t)bh * SEQ * HD;
    const float* Vb = g_V + (size_t)bh * SEQ * HD;

    // q row packed into 32 f32x2 registers
    ull qp[32];
    {
        const float4* qsrc = (const float4*)(Qb + (size_t)(qt * 64 + qr) * HD);
        #pragma unroll
        for (int i = 0; i < 16; i++) {
            float4 v = qsrc[i];
            PK2(qp[2 * i + 0], v.x, v.y);
            PK2(qp[2 * i + 1], v.z, v.w);
        }
    }

    ull o2[32];
    #pragma unroll
    for (int d = 0; d < 32; d++) o2[d] = 0ull;   // two packed +0.0f
    float m = -1e30f, l = 0.f;
    const float scale = 0.125f;

    for (int c = 0; c < 16; c++) {
        __syncthreads();
        {
            const float4* ks = (const float4*)(Kb + (size_t)c * 64 * HD);
            const float4* vs = (const float4*)(Vb + (size_t)c * 64 * HD);
            for (int i = t; i < 1024; i += 128) {
                ((float4*)Ks)[i] = ks[i];
                ((float4*)Vs)[i] = vs[i];
            }
        }
        __syncthreads();

        float p[32];
        float mloc = -1e30f;
        #pragma unroll
        for (int j = 0; j < 32; j++) {
            const int kc = half * 32 + j;
            const double2* kp = (const double2*)(Ks + kc * 64);
            ull a2 = 0ull;
            #pragma unroll
            for (int d4 = 0; d4 < 16; d4++) {
                double2 kd = kp[d4];
                FMA2(a2, qp[2 * d4 + 0], __double_as_longlong(kd.x));
                FMA2(a2, qp[2 * d4 + 1], __double_as_longlong(kd.y));
            }
            float s0, s1;
            UPK2(s0, s1, a2);
            p[j] = (s0 + s1) * scale;
            mloc = fmaxf(mloc, p[j]);
        }
        mloc = fmaxf(mloc, __shfl_xor_sync(0xffffffffu, mloc, 1));
        const float mnew = fmaxf(m, mloc);
        const float corr = __expf(m - mnew);

        float lsum = 0.f;
        #pragma unroll
        for (int j = 0; j < 32; j++) {
            p[j] = __expf(p[j] - mnew);
            lsum += p[j];
        }
        lsum += __shfl_xor_sync(0xffffffffu, lsum, 1);
        l = l * corr + lsum;
        m = mnew;

        ull corrp;
        PK2(corrp, corr, corr);
        #pragma unroll
        for (int d = 0; d < 32; d++) {
            ull tacc = o2[d];
            MUL2(tacc, corrp);
            o2[d] = tacc;
        }

        #pragma unroll
        for (int j = 0; j < 32; j++) {
            const int kc = half * 32 + j;
            const float pv = p[j];
            ull pvp;
            PK2(pvp, pv, pv);
            const double2* vp = (const double2*)(Vs + kc * 64);
            #pragma unroll
            for (int d4 = 0; d4 < 16; d4++) {
                double2 vd = vp[d4];
                ull t0 = o2[2 * d4 + 0];
                ull t1 = o2[2 * d4 + 1];
                FMA2(t0, pvp, __double_as_longlong(vd.x));
                FMA2(t1, pvp, __double_as_longlong(vd.y));
                o2[2 * d4 + 0] = t0;
                o2[2 * d4 + 1] = t1;
            }
        }
    }

    // unpack, combine lane-pair halves, normalize, store
    float o[64];
    #pragma unroll
    for (int d = 0; d < 32; d++)
        UPK2(o[2 * d], o[2 * d + 1], o2[d]);

    #pragma unroll
    for (int d = 0; d < 64; d++)
        o[d] += __shfl_xor_sync(0xffffffffu, o[d], 1);

    const float inv = 1.f / l;
    const int b = bh / HEADS, h = bh % HEADS;
    const int qg = qt * 64 + qr;
    float* op = g_O + ((size_t)(b * SEQ + qg)) * DIMC + h * HD + half * 32;
    #pragma unroll
    for (int d = 0; d < 32; d++) op[d] = o[half * 32 + d] * inv;
}

// ----------------------------------------------------------------------------
// Launch
// ----------------------------------------------------------------------------

extern "C" void kernel_launch(void* const* d_in, const int* in_sizes, int n_in,
                              void* d_out, int out_size)
{
    const float* x      = (const float*)d_in[0];
    const float* w_qkv  = (const float*)d_in[1];
    const float* b_qkv  = (const float*)d_in[2];
    const float* w_proj = (const float*)d_in[3];
    const float* b_proj = (const float*)d_in[4];
    float* out = (float*)d_out;

    gemm_qkv_kernel<<<dim3(NQKV / 128, MROWS / 128), 256>>>(x, w_qkv, b_qkv);
    attn_kernel<<<dim3(BATCH * HEADS, SEQ / 64), 128>>>();
    gemm_proj_kernel<<<dim3(DIMC / 128, MROWS / 128), 256>>>(w_proj, b_proj, out);
}

// round 13
// speedup vs baseline: 1.0988x; 1.0482x over previous
#include <cuda_runtime.h>

// ----------------------------------------------------------------------------
// MultiHeadSelfAttention: B=16, N=1024, C=768, H=12, D=64
// R13 (= R10 resubmit #2; two infra failures in a row): pure SIMT fp32 path.
//  - GEMMs: verbatim R7 (f32x2 packed, passing).
//  - Attention: tiled register-blocked flash kernel: q-tile 32, kc-chunk 64,
//    4x4 microtiles, Q/K/P/V staged in smem (stride 65 -> conflict-free),
//    online softmax via 16-lane shfl groups. Halves smem traffic per FLOP.
// ----------------------------------------------------------------------------

#define DIMC   768
#define HEADS  12
#define HD     64
#define BATCH  16
#define SEQ    1024
#define MROWS  (BATCH * SEQ)   // 16384
#define NQKV   (3 * DIMC)      // 2304
#define QT     32              // q rows per attention block

__device__ float g_Q[(size_t)BATCH * HEADS * SEQ * HD];
__device__ float g_K[(size_t)BATCH * HEADS * SEQ * HD];
__device__ float g_V[(size_t)BATCH * HEADS * SEQ * HD];
__device__ float g_O[(size_t)MROWS * DIMC];

typedef unsigned long long ull;

#define PK2(out, lo, hi) asm("mov.b64 %0, {%1, %2};" : "=l"(out) : "f"(lo), "f"(hi))
#define UPK2(lo, hi, in) asm("mov.b64 {%0, %1}, %2;" : "=f"(lo), "=f"(hi) : "l"(in))
#define FMA2(acc, a, b)  asm("fma.rn.f32x2 %0, %1, %2, %0;" : "+l"(acc) : "l"(a), "l"(b))
#define MUL2(acc, s)     asm("mul.rn.f32x2 %0, %0, %1;" : "+l"(acc) : "l"(s))

// ----------------------------------------------------------------------------
// SGEMM 128x128x8, 256 threads, 8x8 microtile, f32x2 (verbatim R7 - passing).
// ----------------------------------------------------------------------------

__global__ __launch_bounds__(256) void gemm_qkv_kernel(
    const float* __restrict__ X,
    const float* __restrict__ W,
    const float* __restrict__ bias)
{
    __shared__ float As[8][128];
    __shared__ float Bs[8][128];
    const int K  = DIMC;
    const int Nc = NQKV;

    const int t  = threadIdx.x;
    const int bm = blockIdx.y;
    const int bn = blockIdx.x;

    const int arow = t >> 1, acol = (t & 1) * 4;
    const int brow = t >> 5, bcol = (t & 31) * 4;

    const float* Ap = X + (size_t)(bm * 128 + arow) * K + acol;
    const float* Bp = W + (size_t)brow * Nc + bn * 128 + bcol;

    ull acc2[8][4];
    #pragma unroll
    for (int i = 0; i < 8; i++)
        #pragma unroll
        for (int j = 0; j < 4; j++) acc2[i][j] = 0ull;

    const int tx = t & 15, ty = t >> 4;

    for (int k0 = 0; k0 < K; k0 += 8) {
        float4 av = *(const float4*)(Ap + k0);
        float4 bv = *(const float4*)(Bp + (size_t)k0 * Nc);
        As[acol + 0][arow] = av.x;
        As[acol + 1][arow] = av.y;
        As[acol + 2][arow] = av.z;
        As[acol + 3][arow] = av.w;
        *(float4*)&Bs[brow][bcol] = bv;
        __syncthreads();

        #pragma unroll
        for (int kk = 0; kk < 8; kk++) {
            float4 a0 = *(const float4*)&As[kk][ty * 8];
            float4 a1 = *(const float4*)&As[kk][ty * 8 + 4];
            float4 b0 = *(const float4*)&Bs[kk][tx * 8];
            float4 b1 = *(const float4*)&Bs[kk][tx * 8 + 4];
            ull ab[8];
            PK2(ab[0], a0.x, a0.x); PK2(ab[1], a0.y, a0.y);
            PK2(ab[2], a0.z, a0.z); PK2(ab[3], a0.w, a0.w);
            PK2(ab[4], a1.x, a1.x); PK2(ab[5], a1.y, a1.y);
            PK2(ab[6], a1.z, a1.z); PK2(ab[7], a1.w, a1.w);
            ull bp[4];
            PK2(bp[0], b0.x, b0.y); PK2(bp[1], b0.z, b0.w);
            PK2(bp[2], b1.x, b1.y); PK2(bp[3], b1.z, b1.w);
            #pragma unroll
            for (int i = 0; i < 8; i++)
                #pragma unroll
                for (int j = 0; j < 4; j++) {
                    ull tacc = acc2[i][j];
                    FMA2(tacc, ab[i], bp[j]);
                    acc2[i][j] = tacc;
                }
        }
        __syncthreads();
    }

    #pragma unroll
    for (int i = 0; i < 8; i++) {
        const int row = bm * 128 + ty * 8 + i;
        const int bb  = row >> 10;
        const int nn  = row & 1023;
        #pragma unroll
        for (int jp = 0; jp < 4; jp++) {
            float v0, v1;
            UPK2(v0, v1, acc2[i][jp]);
            #pragma unroll
            for (int e = 0; e < 2; e++) {
                const int col = bn * 128 + tx * 8 + 2 * jp + e;
                const float v = (e == 0 ? v0 : v1) + bias[col];
                const int which = col / DIMC;
                const int rem   = col - which * DIMC;
                const int h     = rem >> 6;
                const int d     = rem & 63;
                const size_t idx = (((size_t)(bb * HEADS + h)) * SEQ + nn) * HD + d;
                if (which == 0)      g_Q[idx] = v;
                else if (which == 1) g_K[idx] = v;
                else                 g_V[idx] = v;
            }
        }
    }
}

__global__ __launch_bounds__(256) void gemm_proj_kernel(
    const float* __restrict__ W,
    const float* __restrict__ bias,
    float* __restrict__ out)
{
    __shared__ float As[8][128];
    __shared__ float Bs[8][128];
    const int K  = DIMC;
    const int Nc = DIMC;

    const int t  = threadIdx.x;
    const int bm = blockIdx.y;
    const int bn = blockIdx.x;

    const int arow = t >> 1, acol = (t & 1) * 4;
    const int brow = t >> 5, bcol = (t & 31) * 4;

    const float* Ap = g_O + (size_t)(bm * 128 + arow) * K + acol;
    const float* Bp = W + (size_t)brow * Nc + bn * 128 + bcol;

    ull acc2[8][4];
    #pragma unroll
    for (int i = 0; i < 8; i++)
        #pragma unroll
        for (int j = 0; j < 4; j++) acc2[i][j] = 0ull;

    const int tx = t & 15, ty = t >> 4;

    for (int k0 = 0; k0 < K; k0 += 8) {
        float4 av = *(const float4*)(Ap + k0);
        float4 bv = *(const float4*)(Bp + (size_t)k0 * Nc);
        As[acol + 0][arow] = av.x;
        As[acol + 1][arow] = av.y;
        As[acol + 2][arow] = av.z;
        As[acol + 3][arow] = av.w;
        *(float4*)&Bs[brow][bcol] = bv;
        __syncthreads();

        #pragma unroll
        for (int kk = 0; kk < 8; kk++) {
            float4 a0 = *(const float4*)&As[kk][ty * 8];
            float4 a1 = *(const float4*)&As[kk][ty * 8 + 4];
            float4 b0 = *(const float4*)&Bs[kk][tx * 8];
            float4 b1 = *(const float4*)&Bs[kk][tx * 8 + 4];
            ull ab[8];
            PK2(ab[0], a0.x, a0.x); PK2(ab[1], a0.y, a0.y);
            PK2(ab[2], a0.z, a0.z); PK2(ab[3], a0.w, a0.w);
            PK2(ab[4], a1.x, a1.x); PK2(ab[5], a1.y, a1.y);
            PK2(ab[6], a1.z, a1.z); PK2(ab[7], a1.w, a1.w);
            ull bp[4];
            PK2(bp[0], b0.x, b0.y); PK2(bp[1], b0.z, b0.w);
            PK2(bp[2], b1.x, b1.y); PK2(bp[3], b1.z, b1.w);
            #pragma unroll
            for (int i = 0; i < 8; i++)
                #pragma unroll
                for (int j = 0; j < 4; j++) {
                    ull tacc = acc2[i][j];
                    FMA2(tacc, ab[i], bp[j]);
                    acc2[i][j] = tacc;
                }
        }
        __syncthreads();
    }

    #pragma unroll
    for (int i = 0; i < 8; i++) {
        const int row = bm * 128 + ty * 8 + i;
        #pragma unroll
        for (int jp = 0; jp < 4; jp++) {
            float v0, v1;
            UPK2(v0, v1, acc2[i][jp]);
            const int col = bn * 128 + tx * 8 + 2 * jp;
            out[(size_t)row * Nc + col]     = v0 + bias[col];
            out[(size_t)row * Nc + col + 1] = v1 + bias[col + 1];
        }
    }
}

// ----------------------------------------------------------------------------
// Attention v2: tiled register-blocked flash attention.
// Grid (B*H, SEQ/QT). 128 threads = 8(ty) x 16(tx).
// Thread microtiles: S 4q x 4kc (kc = 16*i+tx), O 4q x 4d (d = 16*i+tx).
// Smem: Qs[32][65] (pre-scaled), KP[64][65] (K chunk, then P), Vs[64][65].
// ----------------------------------------------------------------------------

__global__ __launch_bounds__(128) void attn_kernel()
{
    __shared__ float Qs[QT * 65];
    __shared__ float KP[64 * 65];
    __shared__ float Vs[64 * 65];

    const int bh = blockIdx.x;
    const int qt = blockIdx.y;
    const int t  = threadIdx.x;
    const int tx = t & 15;
    const int ty = t >> 4;
    const int ty4 = ty * 4;

    const float* Qb = g_Q + (size_t)bh * SEQ * HD;
    const float* Kb = g_K + (size_t)bh * SEQ * HD;
    const float* Vb = g_V + (size_t)bh * SEQ * HD;

    // Load Q tile (pre-scaled by 1/8). 2048 floats, 16 per thread.
    {
        const int r  = t >> 2;
        const int c0 = (t & 3) * 16;
        const float4* src = (const float4*)(Qb + (size_t)(qt * QT + r) * HD + c0);
        #pragma unroll
        for (int i = 0; i < 4; i++) {
            float4 v = src[i];
            float* dst = &Qs[r * 65 + c0 + 4 * i];
            dst[0] = v.x * 0.125f; dst[1] = v.y * 0.125f;
            dst[2] = v.z * 0.125f; dst[3] = v.w * 0.125f;
        }
    }

    ull o2[2][4];
    #pragma unroll
    for (int jj = 0; jj < 2; jj++)
        #pragma unroll
        for (int i = 0; i < 4; i++) o2[jj][i] = 0ull;
    float mrow[4] = {-1e30f, -1e30f, -1e30f, -1e30f};
    float lrow[4] = {0.f, 0.f, 0.f, 0.f};

    for (int c = 0; c < SEQ / 64; c++) {
        __syncthreads();   // prior phase-2 readers of KP/Vs done
        // Load K,V chunk (rows c*64 .. +63), 32 floats each per thread.
        {
            const int r  = t >> 1;
            const int c0 = (t & 1) * 32;
            const float4* ks = (const float4*)(Kb + (size_t)(c * 64 + r) * HD + c0);
            const float4* vs = (const float4*)(Vb + (size_t)(c * 64 + r) * HD + c0);
            #pragma unroll
            for (int i = 0; i < 8; i++) {
                float4 kv = ks[i];
                float4 vv = vs[i];
                float* kd = &KP[r * 65 + c0 + 4 * i];
                float* vd = &Vs[r * 65 + c0 + 4 * i];
                kd[0] = kv.x; kd[1] = kv.y; kd[2] = kv.z; kd[3] = kv.w;
                vd[0] = vv.x; vd[1] = vv.y; vd[2] = vv.z; vd[3] = vv.w;
            }
        }
        __syncthreads();

        // Phase 1: S(4q x 4kc) = Qs . K^T   (Q pre-scaled)
        ull s2[2][4];
        #pragma unroll
        for (int jj = 0; jj < 2; jj++)
            #pragma unroll
            for (int i = 0; i < 4; i++) s2[jj][i] = 0ull;

        #pragma unroll 4
        for (int d = 0; d < 64; d++) {
            ull qq0, qq1;
            PK2(qq0, Qs[(ty4 + 0) * 65 + d], Qs[(ty4 + 1) * 65 + d]);
            PK2(qq1, Qs[(ty4 + 2) * 65 + d], Qs[(ty4 + 3) * 65 + d]);
            #pragma unroll
            for (int i = 0; i < 4; i++) {
                const float kv = KP[(16 * i + tx) * 65 + d];
                ull kb;
                PK2(kb, kv, kv);
                ull t0 = s2[0][i]; FMA2(t0, qq0, kb); s2[0][i] = t0;
                ull t1 = s2[1][i]; FMA2(t1, qq1, kb); s2[1][i] = t1;
            }
        }

        float s[4][4];
        #pragma unroll
        for (int jj = 0; jj < 2; jj++)
            #pragma unroll
            for (int i = 0; i < 4; i++)
                UPK2(s[2 * jj][i], s[2 * jj + 1][i], s2[jj][i]);

        // Online softmax stats per q-row (reduce over the 16-lane tx group)
        float corrj[4];
        #pragma unroll
        for (int j = 0; j < 4; j++) {
            float mloc = fmaxf(fmaxf(s[j][0], s[j][1]), fmaxf(s[j][2], s[j][3]));
            mloc = fmaxf(mloc, __shfl_xor_sync(0xffffffffu, mloc, 1));
            mloc = fmaxf(mloc, __shfl_xor_sync(0xffffffffu, mloc, 2));
            mloc = fmaxf(mloc, __shfl_xor_sync(0xffffffffu, mloc, 4));
            mloc = fmaxf(mloc, __shfl_xor_sync(0xffffffffu, mloc, 8));
            const float mnew = fmaxf(mrow[j], mloc);
            corrj[j] = __expf(mrow[j] - mnew);
            float lsum = 0.f;
            #pragma unroll
            for (int i = 0; i < 4; i++) {
                s[j][i] = __expf(s[j][i] - mnew);
                lsum += s[j][i];
            }
            lsum += __shfl_xor_sync(0xffffffffu, lsum, 1);
            lsum += __shfl_xor_sync(0xffffffffu, lsum, 2);
            lsum += __shfl_xor_sync(0xffffffffu, lsum, 4);
            lsum += __shfl_xor_sync(0xffffffffu, lsum, 8);
            lrow[j] = lrow[j] * corrj[j] + lsum;
            mrow[j] = mnew;
        }

        __syncthreads();   // everyone done reading K from KP
        // Write P over K
        #pragma unroll
        for (int j = 0; j < 4; j++)
            #pragma unroll
            for (int i = 0; i < 4; i++)
                KP[(ty4 + j) * 65 + 16 * i + tx] = s[j][i];

        // Rescale O accumulators
        {
            ull c0p, c1p;
            PK2(c0p, corrj[0], corrj[1]);
            PK2(c1p, corrj[2], corrj[3]);
            #pragma unroll
            for (int i = 0; i < 4; i++) {
                ull t0 = o2[0][i]; MUL2(t0, c0p); o2[0][i] = t0;
                ull t1 = o2[1][i]; MUL2(t1, c1p); o2[1][i] = t1;
            }
        }
        __syncthreads();

        // Phase 2: O(4q x 4d) += P . V
        #pragma unroll 4
        for (int kc = 0; kc < 64; kc++) {
            ull pp0, pp1;
            PK2(pp0, KP[(ty4 + 0) * 65 + kc], KP[(ty4 + 1) * 65 + kc]);
            PK2(pp1, KP[(ty4 + 2) * 65 + kc], KP[(ty4 + 3) * 65 + kc]);
            #pragma unroll
            for (int i = 0; i < 4; i++) {
                const float vv = Vs[kc * 65 + 16 * i + tx];
                ull vb;
                PK2(vb, vv, vv);
                ull t0 = o2[0][i]; FMA2(t0, pp0, vb); o2[0][i] = t0;
                ull t1 = o2[1][i]; FMA2(t1, pp1, vb); o2[1][i] = t1;
            }
        }
    }

    // Epilogue: normalize and store
    const int b = bh / HEADS, h = bh - b * HEADS;
    const float inv0 = 1.f / lrow[0];
    const float inv1 = 1.f / lrow[1];
    const float inv2 = 1.f / lrow[2];
    const float inv3 = 1.f / lrow[3];
    #pragma unroll
    for (int jj = 0; jj < 2; jj++) {
        #pragma unroll
        for (int i = 0; i < 4; i++) {
            float oa, ob;
            UPK2(oa, ob, o2[jj][i]);
            const int j0 = 2 * jj, j1 = 2 * jj + 1;
            const float f0 = oa * (jj == 0 ? inv0 : inv2);
            const float f1 = ob * (jj == 0 ? inv1 : inv3);
            const int d = 16 * i + tx;
            const int q0 = qt * QT + ty4 + j0;
            const int q1 = qt * QT + ty4 + j1;
            g_O[((size_t)(b * SEQ + q0)) * DIMC + h * HD + d] = f0;
            g_O[((size_t)(b * SEQ + q1)) * DIMC + h * HD + d] = f1;
        }
    }
}

// ----------------------------------------------------------------------------
// Launch
// ----------------------------------------------------------------------------

extern "C" void kernel_launch(void* const* d_in, const int* in_sizes, int n_in,
                              void* d_out, int out_size)
{
    const float* x      = (const float*)d_in[0];
    const float* w_qkv  = (const float*)d_in[1];
    const float* b_qkv  = (const float*)d_in[2];
    const float* w_proj = (const float*)d_in[3];
    const float* b_proj = (const float*)d_in[4];
    float* out = (float*)d_out;

    gemm_qkv_kernel<<<dim3(NQKV / 128, MROWS / 128), 256>>>(x, w_qkv, b_qkv);
    attn_kernel<<<dim3(BATCH * HEADS, SEQ / QT), 128>>>();
    gemm_proj_kernel<<<dim3(DIMC / 128, MROWS / 128), 256>>>(w_proj, b_proj, out);
}